// round 1
// baseline (speedup 1.0000x reference)
#include <cuda_runtime.h>
#include <cuda_bf16.h>
#include <math.h>

// Problem constants
#define Bq   4
#define Sq   2048
#define Dm   1024
#define Hh   16
#define DKh  64
// q/k/v/ctx scratch: [B, S, H*Dh] row-major, 32MB each (device globals: allowed)
__device__ float g_q[Bq * Sq * Dm];
__device__ float g_k[Bq * Sq * Dm];
__device__ float g_v[Bq * Sq * Dm];
__device__ float g_ctx[Bq * Sq * Dm];

// ---------------------------------------------------------------------------
// Tiled fp32 GEMM with bias: C[M,N] = A[M,K] @ B[K,N] + bias[N]
// 64x64 tile, BK=16, 256 threads, 4x4 microtile per thread.
// ---------------------------------------------------------------------------
__global__ __launch_bounds__(256) void gemm_bias(
    const float* __restrict__ A, const float* __restrict__ B,
    const float* __restrict__ bias, float* __restrict__ C,
    int M, int N, int K)
{
    __shared__ float As[16][68];   // transposed A tile: As[k][row]
    __shared__ float Bs[16][64];   // Bs[k][col]

    const int tid = threadIdx.x;
    const int tx = tid & 15;        // col group
    const int ty = tid >> 4;        // row group
    const int row0 = blockIdx.y * 64;
    const int col0 = blockIdx.x * 64;

    // A-tile loader: thread -> (row ar, 4 consecutive k at ac)
    const int ar = tid >> 2;
    const int ac = (tid & 3) << 2;
    // B-tile loader: thread -> (k row br, 4 consecutive cols at bc)
    const int br = tid >> 4;
    const int bc = (tid & 15) << 2;

    const float* Aptr = A + (size_t)(row0 + ar) * K + ac;
    const float* Bptr = B + (size_t)br * N + col0 + bc;

    float acc[4][4] = {};

    for (int k0 = 0; k0 < K; k0 += 16) {
        float4 av = *(const float4*)(Aptr + k0);
        As[ac + 0][ar] = av.x;
        As[ac + 1][ar] = av.y;
        As[ac + 2][ar] = av.z;
        As[ac + 3][ar] = av.w;
        *(float4*)&Bs[br][bc] = *(const float4*)(Bptr + (size_t)k0 * N);
        __syncthreads();

#pragma unroll
        for (int k = 0; k < 16; k++) {
            float4 a4 = *(float4*)&As[k][ty << 2];
            float4 b4 = *(float4*)&Bs[k][tx << 2];
            float a[4] = {a4.x, a4.y, a4.z, a4.w};
            float b[4] = {b4.x, b4.y, b4.z, b4.w};
#pragma unroll
            for (int i = 0; i < 4; i++)
#pragma unroll
                for (int j = 0; j < 4; j++)
                    acc[i][j] = fmaf(a[i], b[j], acc[i][j]);
        }
        __syncthreads();
    }

    float4 bv4 = *(const float4*)&bias[col0 + (tx << 2)];
    const float bb[4] = {bv4.x, bv4.y, bv4.z, bv4.w};
#pragma unroll
    for (int i = 0; i < 4; i++) {
        float4 o;
        o.x = acc[i][0] + bb[0];
        o.y = acc[i][1] + bb[1];
        o.z = acc[i][2] + bb[2];
        o.w = acc[i][3] + bb[3];
        *(float4*)&C[(size_t)(row0 + (ty << 2) + i) * N + col0 + (tx << 2)] = o;
    }
}

// ---------------------------------------------------------------------------
// Flash-attention over one (b, h, q-tile): 64 q-rows per block, online softmax.
// q/k/v read from g_q/g_k/g_v in [B,S,H*Dh] layout; ctx written to g_ctx in
// [B,S,H*Dh] layout so the output projection is a plain GEMM.
// Additive mask: scores = (q.k)/8 - 1e9*mask.
// ---------------------------------------------------------------------------
#define SPAD 68

__global__ __launch_bounds__(256) void attn_kernel(
    const float* __restrict__ mask)
{
    extern __shared__ float sm[];
    float* Qts = sm;                 // [64 d][68] Qts[d][row]   (pre-scaled by 1/8)
    float* Kts = sm + 64 * SPAD;     // [64 d][68] Kts[d][col]
    float* Vs  = sm + 2 * 64 * SPAD; // [64 k][68] Vs[k][d]
    float* Pts = sm + 3 * 64 * SPAD; // [64 k][68] Pts[k][row]

    const int bh = blockIdx.y;
    const int b  = bh >> 4;
    const int h  = bh & 15;
    const int q0 = blockIdx.x << 6;

    const int tid = threadIdx.x;
    const int tx = tid & 15;
    const int ty = tid >> 4;

    const float* Qg = g_q + (size_t)(b * Sq) * Dm + h * DKh;
    const float* Kg = g_k + (size_t)(b * Sq) * Dm + h * DKh;
    const float* Vg = g_v + (size_t)(b * Sq) * Dm + h * DKh;

    // Load Q tile transposed, pre-scaled by 1/sqrt(DK)=0.125
#pragma unroll
    for (int l = 0; l < 4; l++) {
        int idx = tid + l * 256;        // 1024 float4 units total
        int r  = idx >> 4;
        int d0 = (idx & 15) << 2;
        float4 v = *(const float4*)(Qg + (size_t)(q0 + r) * Dm + d0);
        Qts[(d0 + 0) * SPAD + r] = v.x * 0.125f;
        Qts[(d0 + 1) * SPAD + r] = v.y * 0.125f;
        Qts[(d0 + 2) * SPAD + r] = v.z * 0.125f;
        Qts[(d0 + 3) * SPAD + r] = v.w * 0.125f;
    }

    float m_i[4], l_i[4], acc[4][4];
#pragma unroll
    for (int i = 0; i < 4; i++) {
        m_i[i] = -1e30f;
        l_i[i] = 0.f;
#pragma unroll
        for (int j = 0; j < 4; j++) acc[i][j] = 0.f;
    }

    for (int kt = 0; kt < Sq / 64; kt++) {
        const int k0 = kt << 6;
        __syncthreads();   // previous iteration's smem reads done
        // Load K (transposed) and V tiles
#pragma unroll
        for (int l = 0; l < 4; l++) {
            int idx = tid + l * 256;
            int r  = idx >> 4;
            int d0 = (idx & 15) << 2;
            float4 kv = *(const float4*)(Kg + (size_t)(k0 + r) * Dm + d0);
            Kts[(d0 + 0) * SPAD + r] = kv.x;
            Kts[(d0 + 1) * SPAD + r] = kv.y;
            Kts[(d0 + 2) * SPAD + r] = kv.z;
            Kts[(d0 + 3) * SPAD + r] = kv.w;
            float4 vv = *(const float4*)(Vg + (size_t)(k0 + r) * Dm + d0);
            *(float4*)&Vs[r * SPAD + d0] = vv;
        }
        __syncthreads();

        // S = Qs @ Ks^T  (already scaled)
        float s[4][4] = {};
#pragma unroll 16
        for (int d = 0; d < 64; d++) {
            float4 a4 = *(float4*)&Qts[d * SPAD + (ty << 2)];
            float4 b4 = *(float4*)&Kts[d * SPAD + (tx << 2)];
            float a[4] = {a4.x, a4.y, a4.z, a4.w};
            float bb[4] = {b4.x, b4.y, b4.z, b4.w};
#pragma unroll
            for (int i = 0; i < 4; i++)
#pragma unroll
                for (int j = 0; j < 4; j++)
                    s[i][j] = fmaf(a[i], bb[j], s[i][j]);
        }

        // Additive mask
#pragma unroll
        for (int i = 0; i < 4; i++) {
            const int r = (ty << 2) + i;
            const float* mrow = mask + (size_t)(q0 + r) * Sq + k0 + (tx << 2);
#pragma unroll
            for (int j = 0; j < 4; j++)
                s[i][j] = fmaf(mrow[j], -1e9f, s[i][j]);
        }

        // Online softmax update + P staging (transposed)
#pragma unroll
        for (int i = 0; i < 4; i++) {
            float mx = fmaxf(fmaxf(s[i][0], s[i][1]), fmaxf(s[i][2], s[i][3]));
#pragma unroll
            for (int o = 1; o < 16; o <<= 1)
                mx = fmaxf(mx, __shfl_xor_sync(0xffffffffu, mx, o));
            float mnew = fmaxf(m_i[i], mx);
            float corr = __expf(m_i[i] - mnew);
            float rs = 0.f;
#pragma unroll
            for (int j = 0; j < 4; j++) {
                float p = __expf(s[i][j] - mnew);
                s[i][j] = p;
                rs += p;
            }
#pragma unroll
            for (int o = 1; o < 16; o <<= 1)
                rs += __shfl_xor_sync(0xffffffffu, rs, o);
            l_i[i] = l_i[i] * corr + rs;
            m_i[i] = mnew;
#pragma unroll
            for (int j = 0; j < 4; j++) acc[i][j] *= corr;
#pragma unroll
            for (int j = 0; j < 4; j++)
                Pts[((tx << 2) + j) * SPAD + (ty << 2) + i] = s[i][j];
        }
        __syncthreads();

        // acc += P @ V
#pragma unroll 16
        for (int k = 0; k < 64; k++) {
            float4 a4 = *(float4*)&Pts[k * SPAD + (ty << 2)];
            float4 b4 = *(float4*)&Vs[k * SPAD + (tx << 2)];
            float a[4] = {a4.x, a4.y, a4.z, a4.w};
            float bb[4] = {b4.x, b4.y, b4.z, b4.w};
#pragma unroll
            for (int i = 0; i < 4; i++)
#pragma unroll
                for (int j = 0; j < 4; j++)
                    acc[i][j] = fmaf(a[i], bb[j], acc[i][j]);
        }
    }

    // Epilogue: normalize, write ctx [B,S,H*DV]
#pragma unroll
    for (int i = 0; i < 4; i++) {
        float inv = 1.f / l_i[i];
        float4 o;
        o.x = acc[i][0] * inv;
        o.y = acc[i][1] * inv;
        o.z = acc[i][2] * inv;
        o.w = acc[i][3] * inv;
        const int r = q0 + (ty << 2) + i;
        *(float4*)&g_ctx[(size_t)(b * Sq + r) * Dm + h * DKh + (tx << 2)] = o;
    }
}

// ---------------------------------------------------------------------------
// kernel_launch: QKV GEMMs -> flash attention -> output GEMM
// ---------------------------------------------------------------------------
extern "C" void kernel_launch(void* const* d_in, const int* in_sizes, int n_in,
                              void* d_out, int out_size)
{
    const float* queries = (const float*)d_in[0];
    const float* keys    = (const float*)d_in[1];
    const float* values  = (const float*)d_in[2];
    const float* mask    = (const float*)d_in[3];
    const float* Wq = (const float*)d_in[4];
    const float* bq = (const float*)d_in[5];
    const float* Wk = (const float*)d_in[6];
    const float* bk = (const float*)d_in[7];
    const float* Wv = (const float*)d_in[8];
    const float* bv = (const float*)d_in[9];
    const float* Wo = (const float*)d_in[10];
    const float* bo = (const float*)d_in[11];
    float* out = (float*)d_out;

    float *pq, *pk, *pv, *pctx;
    cudaGetSymbolAddress((void**)&pq,   g_q);
    cudaGetSymbolAddress((void**)&pk,   g_k);
    cudaGetSymbolAddress((void**)&pv,   g_v);
    cudaGetSymbolAddress((void**)&pctx, g_ctx);

    const int M = Bq * Sq;   // 8192
    const int N = Dm;        // 1024
    const int K = Dm;        // 1024

    dim3 gblk(256);
    dim3 ggrid(N / 64, M / 64);

    // QKV projections
    gemm_bias<<<ggrid, gblk>>>(queries, Wq, bq, pq, M, N, K);
    gemm_bias<<<ggrid, gblk>>>(keys,    Wk, bk, pk, M, N, K);
    gemm_bias<<<ggrid, gblk>>>(values,  Wv, bv, pv, M, N, K);

    // Flash attention
    const int smem = 4 * 64 * SPAD * (int)sizeof(float);  // 69632 B
    cudaFuncSetAttribute(attn_kernel, cudaFuncAttributeMaxDynamicSharedMemorySize, smem);
    dim3 agrid(Sq / 64, Bq * Hh);
    attn_kernel<<<agrid, gblk, smem>>>(mask);

    // Output projection
    gemm_bias<<<ggrid, gblk>>>(pctx, Wo, bo, out, M, N, K);
}

// round 3
// speedup vs baseline: 1.3527x; 1.3527x over previous
#include <cuda_runtime.h>
#include <cuda_bf16.h>
#include <cstdint>
#include <math.h>

// Problem constants
#define Bq   4
#define Sq   2048
#define Dm   1024
#define Hh   16
#define DKh  64

// q/k/v/ctx scratch: [B, S, H*Dh] row-major (device globals: allowed)
__device__ float g_q[Bq * Sq * Dm];
__device__ float g_k[Bq * Sq * Dm];
__device__ float g_v[Bq * Sq * Dm];
__device__ float g_ctx[Bq * Sq * Dm];

// ===========================================================================
// warp-level MMA helpers (baseline PTX, legal in compute_103)
// ===========================================================================
__device__ __forceinline__ uint32_t smem_u32(const void* p) {
    uint32_t a;
    asm("{ .reg .u64 t; cvta.to.shared.u64 t, %1; cvt.u32.u64 %0, t; }"
        : "=r"(a) : "l"(p));
    return a;
}

__device__ __forceinline__ void ldm_x4(uint32_t* r, uint32_t addr) {
    asm volatile("ldmatrix.sync.aligned.m8n8.x4.shared.b16 {%0,%1,%2,%3}, [%4];"
                 : "=r"(r[0]), "=r"(r[1]), "=r"(r[2]), "=r"(r[3]) : "r"(addr));
}
__device__ __forceinline__ void ldm_x2(uint32_t* r, uint32_t addr) {
    asm volatile("ldmatrix.sync.aligned.m8n8.x2.shared.b16 {%0,%1}, [%2];"
                 : "=r"(r[0]), "=r"(r[1]) : "r"(addr));
}
__device__ __forceinline__ void mma_bf16(float* c, const uint32_t* a, const uint32_t* b) {
    asm volatile(
        "mma.sync.aligned.m16n8k16.row.col.f32.bf16.bf16.f32 "
        "{%0,%1,%2,%3}, {%4,%5,%6,%7}, {%8,%9}, {%0,%1,%2,%3};"
        : "+f"(c[0]), "+f"(c[1]), "+f"(c[2]), "+f"(c[3])
        : "r"(a[0]), "r"(a[1]), "r"(a[2]), "r"(a[3]), "r"(b[0]), "r"(b[1]));
}

// ===========================================================================
// bf16x3 split-precision GEMM + bias via mma.sync (HMMA path)
// C[M,N] = A[M,K] @ W[K,N] + bias
// CTA: 128x128 C tile, BK=64, 256 threads = 8 warps (2m x 4n), warp: 64x32.
// smem: K-major bf16 tiles, row stride 72 bf16 (144B) for conflict-free ldmatrix
// ===========================================================================
#define BK      64
#define LDT     72                         // padded row stride in bf16
#define A_TILE  (128 * LDT * 2)            // 18432 B
#define B_TILE  (128 * LDT * 2)            // 18432 B (128 n rows x 64 k)
#define SM_A_HI 0
#define SM_A_LO (SM_A_HI + A_TILE)
#define SM_B_HI (SM_A_LO + A_TILE)
#define SM_B_LO (SM_B_HI + B_TILE)
#define SM_GEMM_TOTAL (SM_B_LO + B_TILE)   // 73728 B

__global__ __launch_bounds__(256) void gemm_tc(
    const float* __restrict__ A, const float* __restrict__ W,
    const float* __restrict__ bias, float* __restrict__ C,
    int M, int N, int K)
{
    extern __shared__ char sm[];
    const uint32_t smb = smem_u32(sm);
    const int tid = threadIdx.x;
    const int wid = tid >> 5;
    const int lane = tid & 31;
    const int wm = wid >> 2;        // 0..1
    const int wn = wid & 3;         // 0..3

    const int m0 = blockIdx.y << 7;
    const int n0 = blockIdx.x << 7;

    float c[4][4][4];               // [mtile][ntile][reg]
#pragma unroll
    for (int i = 0; i < 4; i++)
#pragma unroll
        for (int j = 0; j < 4; j++)
#pragma unroll
            for (int r = 0; r < 4; r++) c[i][j][r] = 0.f;

    // ldmatrix per-lane addresses (byte offsets within a tile)
    // A frag (m16k16, x4): row = row0 + (lane&15), 16B col = (lane>>4)
    const uint32_t a_lrow = (uint32_t)(lane & 15);
    const uint32_t a_lcol = (uint32_t)(lane >> 4) * 16u;
    // B frag (n8k16, x2): row = col0 + (lane&7), 16B col = (lane>>3)&1
    const uint32_t b_lrow = (uint32_t)(lane & 7);
    const uint32_t b_lcol = (uint32_t)((lane >> 3) & 1) * 16u;

    for (int k0 = 0; k0 < K; k0 += BK) {
        // ---- stage A tile [128 m][64 k] -> split bf16 hi/lo, K-major
#pragma unroll
        for (int l = 0; l < 8; l++) {
            int idx = tid + (l << 8);
            int r  = idx >> 4;             // 0..127
            int c4 = (idx & 15) << 2;      // 0..60
            float4 a = *(const float4*)(A + (size_t)(m0 + r) * K + k0 + c4);
            float av[4] = {a.x, a.y, a.z, a.w};
            __nv_bfloat162 h01, h23, l01, l23;
            h01.x = __float2bfloat16(av[0]);
            h01.y = __float2bfloat16(av[1]);
            h23.x = __float2bfloat16(av[2]);
            h23.y = __float2bfloat16(av[3]);
            l01.x = __float2bfloat16(av[0] - __bfloat162float(h01.x));
            l01.y = __float2bfloat16(av[1] - __bfloat162float(h01.y));
            l23.x = __float2bfloat16(av[2] - __bfloat162float(h23.x));
            l23.y = __float2bfloat16(av[3] - __bfloat162float(h23.y));
            uint32_t off = (uint32_t)(r * LDT + c4) * 2u;
            *(uint2*)(sm + SM_A_HI + off) =
                make_uint2(*(uint32_t*)&h01, *(uint32_t*)&h23);
            *(uint2*)(sm + SM_A_LO + off) =
                make_uint2(*(uint32_t*)&l01, *(uint32_t*)&l23);
        }

        // ---- stage W tile [64 k][128 n] -> Bs[n][k] split bf16 hi/lo
        // thread: 4 consecutive k at one n; lanes sweep n (coalesced reads)
#pragma unroll
        for (int l = 0; l < 8; l++) {
            int n  = (tid & 31) + ((l & 3) << 5);               // 0..127
            int kb = (((tid >> 5) + ((l >> 2) << 3)) << 2);     // 0..60
            const float* wp = W + (size_t)(k0 + kb) * N + n0 + n;
            float v0 = wp[0];
            float v1 = wp[N];
            float v2 = wp[2 * N];
            float v3 = wp[3 * N];
            __nv_bfloat162 h01, h23, l01, l23;
            h01.x = __float2bfloat16(v0);
            h01.y = __float2bfloat16(v1);
            h23.x = __float2bfloat16(v2);
            h23.y = __float2bfloat16(v3);
            l01.x = __float2bfloat16(v0 - __bfloat162float(h01.x));
            l01.y = __float2bfloat16(v1 - __bfloat162float(h01.y));
            l23.x = __float2bfloat16(v2 - __bfloat162float(h23.x));
            l23.y = __float2bfloat16(v3 - __bfloat162float(h23.y));
            uint32_t off = (uint32_t)(n * LDT + kb) * 2u;
            *(uint2*)(sm + SM_B_HI + off) =
                make_uint2(*(uint32_t*)&h01, *(uint32_t*)&h23);
            *(uint2*)(sm + SM_B_LO + off) =
                make_uint2(*(uint32_t*)&l01, *(uint32_t*)&l23);
        }
        __syncthreads();

        // ---- compute: 4 k16-steps
#pragma unroll
        for (int ks = 0; ks < 4; ks++) {
            const uint32_t kbyte = (uint32_t)ks * 32u;
            uint32_t ah[4][4], al[4][4], bh[4][2], bl[4][2];
#pragma unroll
            for (int mt = 0; mt < 4; mt++) {
                uint32_t row = (uint32_t)(wm * 64 + mt * 16) + a_lrow;
                uint32_t addr = row * (LDT * 2u) + a_lcol + kbyte;
                ldm_x4(ah[mt], smb + SM_A_HI + addr);
                ldm_x4(al[mt], smb + SM_A_LO + addr);
            }
#pragma unroll
            for (int nt = 0; nt < 4; nt++) {
                uint32_t row = (uint32_t)(wn * 32 + nt * 8) + b_lrow;
                uint32_t addr = row * (LDT * 2u) + b_lcol + kbyte;
                ldm_x2(bh[nt], smb + SM_B_HI + addr);
                ldm_x2(bl[nt], smb + SM_B_LO + addr);
            }
#pragma unroll
            for (int mt = 0; mt < 4; mt++)
#pragma unroll
                for (int nt = 0; nt < 4; nt++) {
                    mma_bf16(c[mt][nt], ah[mt], bh[nt]);
                    mma_bf16(c[mt][nt], ah[mt], bl[nt]);
                    mma_bf16(c[mt][nt], al[mt], bh[nt]);
                }
        }
        __syncthreads();
    }

    // ---- epilogue: write C + bias
    const int crow = lane >> 2;          // 0..7
    const int ccol = (lane & 3) << 1;    // 0,2,4,6
#pragma unroll
    for (int mt = 0; mt < 4; mt++) {
        const int mbase = m0 + wm * 64 + mt * 16 + crow;
#pragma unroll
        for (int nt = 0; nt < 4; nt++) {
            const int nb = n0 + wn * 32 + nt * 8 + ccol;
            float b0 = bias[nb], b1 = bias[nb + 1];
            float2* p0 = (float2*)(C + (size_t)mbase * N + nb);
            float2* p1 = (float2*)(C + (size_t)(mbase + 8) * N + nb);
            *p0 = make_float2(c[mt][nt][0] + b0, c[mt][nt][1] + b1);
            *p1 = make_float2(c[mt][nt][2] + b0, c[mt][nt][3] + b1);
        }
    }
}

// ---------------------------------------------------------------------------
// Flash-attention (unchanged): 64 q-rows per block, online softmax.
// ---------------------------------------------------------------------------
#define SPAD 68

__global__ __launch_bounds__(256) void attn_kernel(
    const float* __restrict__ mask)
{
    extern __shared__ float smf[];
    float* Qts = smf;                 // [64 d][68] Qts[d][row]   (pre-scaled by 1/8)
    float* Kts = smf + 64 * SPAD;     // [64 d][68] Kts[d][col]
    float* Vs  = smf + 2 * 64 * SPAD; // [64 k][68] Vs[k][d]
    float* Pts = smf + 3 * 64 * SPAD; // [64 k][68] Pts[k][row]

    const int bh = blockIdx.y;
    const int b  = bh >> 4;
    const int h  = bh & 15;
    const int q0 = blockIdx.x << 6;

    const int tid = threadIdx.x;
    const int tx = tid & 15;
    const int ty = tid >> 4;

    const float* Qg = g_q + (size_t)(b * Sq) * Dm + h * DKh;
    const float* Kg = g_k + (size_t)(b * Sq) * Dm + h * DKh;
    const float* Vg = g_v + (size_t)(b * Sq) * Dm + h * DKh;

#pragma unroll
    for (int l = 0; l < 4; l++) {
        int idx = tid + l * 256;
        int r  = idx >> 4;
        int d0 = (idx & 15) << 2;
        float4 v = *(const float4*)(Qg + (size_t)(q0 + r) * Dm + d0);
        Qts[(d0 + 0) * SPAD + r] = v.x * 0.125f;
        Qts[(d0 + 1) * SPAD + r] = v.y * 0.125f;
        Qts[(d0 + 2) * SPAD + r] = v.z * 0.125f;
        Qts[(d0 + 3) * SPAD + r] = v.w * 0.125f;
    }

    float m_i[4], l_i[4], acc[4][4];
#pragma unroll
    for (int i = 0; i < 4; i++) {
        m_i[i] = -1e30f;
        l_i[i] = 0.f;
#pragma unroll
        for (int j = 0; j < 4; j++) acc[i][j] = 0.f;
    }

    for (int kt = 0; kt < Sq / 64; kt++) {
        const int k0 = kt << 6;
        __syncthreads();
#pragma unroll
        for (int l = 0; l < 4; l++) {
            int idx = tid + l * 256;
            int r  = idx >> 4;
            int d0 = (idx & 15) << 2;
            float4 kv = *(const float4*)(Kg + (size_t)(k0 + r) * Dm + d0);
            Kts[(d0 + 0) * SPAD + r] = kv.x;
            Kts[(d0 + 1) * SPAD + r] = kv.y;
            Kts[(d0 + 2) * SPAD + r] = kv.z;
            Kts[(d0 + 3) * SPAD + r] = kv.w;
            float4 vv = *(const float4*)(Vg + (size_t)(k0 + r) * Dm + d0);
            *(float4*)&Vs[r * SPAD + d0] = vv;
        }
        __syncthreads();

        float s[4][4] = {};
#pragma unroll 16
        for (int d = 0; d < 64; d++) {
            float4 a4 = *(float4*)&Qts[d * SPAD + (ty << 2)];
            float4 b4 = *(float4*)&Kts[d * SPAD + (tx << 2)];
            float a[4] = {a4.x, a4.y, a4.z, a4.w};
            float bb[4] = {b4.x, b4.y, b4.z, b4.w};
#pragma unroll
            for (int i = 0; i < 4; i++)
#pragma unroll
                for (int j = 0; j < 4; j++)
                    s[i][j] = fmaf(a[i], bb[j], s[i][j]);
        }

#pragma unroll
        for (int i = 0; i < 4; i++) {
            const int r = (ty << 2) + i;
            const float* mrow = mask + (size_t)(q0 + r) * Sq + k0 + (tx << 2);
#pragma unroll
            for (int j = 0; j < 4; j++)
                s[i][j] = fmaf(mrow[j], -1e9f, s[i][j]);
        }

#pragma unroll
        for (int i = 0; i < 4; i++) {
            float mx = fmaxf(fmaxf(s[i][0], s[i][1]), fmaxf(s[i][2], s[i][3]));
#pragma unroll
            for (int o = 1; o < 16; o <<= 1)
                mx = fmaxf(mx, __shfl_xor_sync(0xffffffffu, mx, o));
            float mnew = fmaxf(m_i[i], mx);
            float corr = __expf(m_i[i] - mnew);
            float rs = 0.f;
#pragma unroll
            for (int j = 0; j < 4; j++) {
                float p = __expf(s[i][j] - mnew);
                s[i][j] = p;
                rs += p;
            }
#pragma unroll
            for (int o = 1; o < 16; o <<= 1)
                rs += __shfl_xor_sync(0xffffffffu, rs, o);
            l_i[i] = l_i[i] * corr + rs;
            m_i[i] = mnew;
#pragma unroll
            for (int j = 0; j < 4; j++) acc[i][j] *= corr;
#pragma unroll
            for (int j = 0; j < 4; j++)
                Pts[((tx << 2) + j) * SPAD + (ty << 2) + i] = s[i][j];
        }
        __syncthreads();

#pragma unroll 16
        for (int k = 0; k < 64; k++) {
            float4 a4 = *(float4*)&Pts[k * SPAD + (ty << 2)];
            float4 b4 = *(float4*)&Vs[k * SPAD + (tx << 2)];
            float a[4] = {a4.x, a4.y, a4.z, a4.w};
            float bb[4] = {b4.x, b4.y, b4.z, b4.w};
#pragma unroll
            for (int i = 0; i < 4; i++)
#pragma unroll
                for (int j = 0; j < 4; j++)
                    acc[i][j] = fmaf(a[i], bb[j], acc[i][j]);
        }
    }

#pragma unroll
    for (int i = 0; i < 4; i++) {
        float inv = 1.f / l_i[i];
        float4 o;
        o.x = acc[i][0] * inv;
        o.y = acc[i][1] * inv;
        o.z = acc[i][2] * inv;
        o.w = acc[i][3] * inv;
        const int r = q0 + (ty << 2) + i;
        *(float4*)&g_ctx[(size_t)(b * Sq + r) * Dm + h * DKh + (tx << 2)] = o;
    }
}

// ---------------------------------------------------------------------------
// kernel_launch: QKV GEMMs (HMMA) -> flash attention -> output GEMM (HMMA)
// ---------------------------------------------------------------------------
extern "C" void kernel_launch(void* const* d_in, const int* in_sizes, int n_in,
                              void* d_out, int out_size)
{
    const float* queries = (const float*)d_in[0];
    const float* keys    = (const float*)d_in[1];
    const float* values  = (const float*)d_in[2];
    const float* mask    = (const float*)d_in[3];
    const float* Wq = (const float*)d_in[4];
    const float* bq = (const float*)d_in[5];
    const float* Wk = (const float*)d_in[6];
    const float* bk = (const float*)d_in[7];
    const float* Wv = (const float*)d_in[8];
    const float* bv = (const float*)d_in[9];
    const float* Wo = (const float*)d_in[10];
    const float* bo = (const float*)d_in[11];
    float* out = (float*)d_out;

    float *pq, *pk, *pv, *pctx;
    cudaGetSymbolAddress((void**)&pq,   g_q);
    cudaGetSymbolAddress((void**)&pk,   g_k);
    cudaGetSymbolAddress((void**)&pv,   g_v);
    cudaGetSymbolAddress((void**)&pctx, g_ctx);

    const int M = Bq * Sq;   // 8192
    const int N = Dm;        // 1024
    const int K = Dm;        // 1024

    cudaFuncSetAttribute(gemm_tc, cudaFuncAttributeMaxDynamicSharedMemorySize,
                         SM_GEMM_TOTAL);
    dim3 gblk(256);
    dim3 ggrid(N / 128, M / 128);   // (8, 64)

    // QKV projections on tensor cores (HMMA)
    gemm_tc<<<ggrid, gblk, SM_GEMM_TOTAL>>>(queries, Wq, bq, pq, M, N, K);
    gemm_tc<<<ggrid, gblk, SM_GEMM_TOTAL>>>(keys,    Wk, bk, pk, M, N, K);
    gemm_tc<<<ggrid, gblk, SM_GEMM_TOTAL>>>(values,  Wv, bv, pv, M, N, K);

    // Flash attention (fp32 SIMT, unchanged)
    const int smem = 4 * 64 * SPAD * (int)sizeof(float);  // 69632 B
    cudaFuncSetAttribute(attn_kernel, cudaFuncAttributeMaxDynamicSharedMemorySize, smem);
    dim3 agrid(Sq / 64, Bq * Hh);
    attn_kernel<<<agrid, gblk, smem>>>(mask);

    // Output projection on tensor cores (HMMA)
    gemm_tc<<<ggrid, gblk, SM_GEMM_TOTAL>>>(pctx, Wo, bo, out, M, N, K);
}

// round 5
// speedup vs baseline: 2.5427x; 1.8798x over previous
#include <cuda_runtime.h>
#include <cuda_bf16.h>
#include <cstdint>
#include <math.h>

// Problem constants
#define Bq   4
#define Sq   2048
#define Dm   1024
#define Hh   16
#define DKh  64

// q/k/v/ctx scratch: [B, S, H*Dh] row-major (device globals: allowed)
__device__ float g_q[Bq * Sq * Dm];
__device__ float g_k[Bq * Sq * Dm];
__device__ float g_v[Bq * Sq * Dm];
__device__ float g_ctx[Bq * Sq * Dm];

// ===========================================================================
// warp-level MMA helpers (baseline PTX, legal in compute_103)
// ===========================================================================
__device__ __forceinline__ uint32_t smem_u32(const void* p) {
    uint32_t a;
    asm("{ .reg .u64 t; cvta.to.shared.u64 t, %1; cvt.u32.u64 %0, t; }"
        : "=r"(a) : "l"(p));
    return a;
}

__device__ __forceinline__ void ldm_x4(uint32_t* r, uint32_t addr) {
    asm volatile("ldmatrix.sync.aligned.m8n8.x4.shared.b16 {%0,%1,%2,%3}, [%4];"
                 : "=r"(r[0]), "=r"(r[1]), "=r"(r[2]), "=r"(r[3]) : "r"(addr));
}
__device__ __forceinline__ void ldm_x2(uint32_t* r, uint32_t addr) {
    asm volatile("ldmatrix.sync.aligned.m8n8.x2.shared.b16 {%0,%1}, [%2];"
                 : "=r"(r[0]), "=r"(r[1]) : "r"(addr));
}
__device__ __forceinline__ void mma_bf16(float* c, const uint32_t* a, const uint32_t* b) {
    asm volatile(
        "mma.sync.aligned.m16n8k16.row.col.f32.bf16.bf16.f32 "
        "{%0,%1,%2,%3}, {%4,%5,%6,%7}, {%8,%9}, {%0,%1,%2,%3};"
        : "+f"(c[0]), "+f"(c[1]), "+f"(c[2]), "+f"(c[3])
        : "r"(a[0]), "r"(a[1]), "r"(a[2]), "r"(a[3]), "r"(b[0]), "r"(b[1]));
}

// split a pair of fp32 into packed bf16x2 hi + bf16x2 lo
__device__ __forceinline__ void split2(float a, float b, uint32_t& hi, uint32_t& lo) {
    __nv_bfloat162 h = __float22bfloat162_rn(make_float2(a, b));
    float ra = a - __bfloat162float(h.x);
    float rb = b - __bfloat162float(h.y);
    __nv_bfloat162 l = __float22bfloat162_rn(make_float2(ra, rb));
    hi = *(uint32_t*)&h;
    lo = *(uint32_t*)&l;
}

// ===========================================================================
// bf16x3 split-precision GEMM + bias via mma.sync (HMMA path)  [unchanged R3]
// ===========================================================================
#define BK      64
#define LDT     72
#define A_TILE  (128 * LDT * 2)
#define B_TILE  (128 * LDT * 2)
#define SM_A_HI 0
#define SM_A_LO (SM_A_HI + A_TILE)
#define SM_B_HI (SM_A_LO + A_TILE)
#define SM_B_LO (SM_B_HI + B_TILE)
#define SM_GEMM_TOTAL (SM_B_LO + B_TILE)   // 73728 B

__global__ __launch_bounds__(256) void gemm_tc(
    const float* __restrict__ A, const float* __restrict__ W,
    const float* __restrict__ bias, float* __restrict__ C,
    int M, int N, int K)
{
    extern __shared__ char sm[];
    const uint32_t smb = smem_u32(sm);
    const int tid = threadIdx.x;
    const int wid = tid >> 5;
    const int lane = tid & 31;
    const int wm = wid >> 2;
    const int wn = wid & 3;

    const int m0 = blockIdx.y << 7;
    const int n0 = blockIdx.x << 7;

    float c[4][4][4];
#pragma unroll
    for (int i = 0; i < 4; i++)
#pragma unroll
        for (int j = 0; j < 4; j++)
#pragma unroll
            for (int r = 0; r < 4; r++) c[i][j][r] = 0.f;

    const uint32_t a_lrow = (uint32_t)(lane & 15);
    const uint32_t a_lcol = (uint32_t)(lane >> 4) * 16u;
    const uint32_t b_lrow = (uint32_t)(lane & 7);
    const uint32_t b_lcol = (uint32_t)((lane >> 3) & 1) * 16u;

    for (int k0 = 0; k0 < K; k0 += BK) {
#pragma unroll
        for (int l = 0; l < 8; l++) {
            int idx = tid + (l << 8);
            int r  = idx >> 4;
            int c4 = (idx & 15) << 2;
            float4 a = *(const float4*)(A + (size_t)(m0 + r) * K + k0 + c4);
            uint32_t h01, h23, l01, l23;
            split2(a.x, a.y, h01, l01);
            split2(a.z, a.w, h23, l23);
            uint32_t off = (uint32_t)(r * LDT + c4) * 2u;
            *(uint2*)(sm + SM_A_HI + off) = make_uint2(h01, h23);
            *(uint2*)(sm + SM_A_LO + off) = make_uint2(l01, l23);
        }
#pragma unroll
        for (int l = 0; l < 8; l++) {
            int n  = (tid & 31) + ((l & 3) << 5);
            int kb = (((tid >> 5) + ((l >> 2) << 3)) << 2);
            const float* wp = W + (size_t)(k0 + kb) * N + n0 + n;
            float v0 = wp[0];
            float v1 = wp[N];
            float v2 = wp[2 * N];
            float v3 = wp[3 * N];
            uint32_t h01, h23, l01, l23;
            split2(v0, v1, h01, l01);
            split2(v2, v3, h23, l23);
            uint32_t off = (uint32_t)(n * LDT + kb) * 2u;
            *(uint2*)(sm + SM_B_HI + off) = make_uint2(h01, h23);
            *(uint2*)(sm + SM_B_LO + off) = make_uint2(l01, l23);
        }
        __syncthreads();

#pragma unroll
        for (int ks = 0; ks < 4; ks++) {
            const uint32_t kbyte = (uint32_t)ks * 32u;
            uint32_t ah[4][4], al[4][4], bh[4][2], bl[4][2];
#pragma unroll
            for (int mt = 0; mt < 4; mt++) {
                uint32_t row = (uint32_t)(wm * 64 + mt * 16) + a_lrow;
                uint32_t addr = row * (LDT * 2u) + a_lcol + kbyte;
                ldm_x4(ah[mt], smb + SM_A_HI + addr);
                ldm_x4(al[mt], smb + SM_A_LO + addr);
            }
#pragma unroll
            for (int nt = 0; nt < 4; nt++) {
                uint32_t row = (uint32_t)(wn * 32 + nt * 8) + b_lrow;
                uint32_t addr = row * (LDT * 2u) + b_lcol + kbyte;
                ldm_x2(bh[nt], smb + SM_B_HI + addr);
                ldm_x2(bl[nt], smb + SM_B_LO + addr);
            }
#pragma unroll
            for (int mt = 0; mt < 4; mt++)
#pragma unroll
                for (int nt = 0; nt < 4; nt++) {
                    mma_bf16(c[mt][nt], ah[mt], bh[nt]);
                    mma_bf16(c[mt][nt], ah[mt], bl[nt]);
                    mma_bf16(c[mt][nt], al[mt], bh[nt]);
                }
        }
        __syncthreads();
    }

    const int crow = lane >> 2;
    const int ccol = (lane & 3) << 1;
#pragma unroll
    for (int mt = 0; mt < 4; mt++) {
        const int mbase = m0 + wm * 64 + mt * 16 + crow;
#pragma unroll
        for (int nt = 0; nt < 4; nt++) {
            const int nb = n0 + wn * 32 + nt * 8 + ccol;
            float b0 = bias[nb], b1 = bias[nb + 1];
            float2* p0 = (float2*)(C + (size_t)mbase * N + nb);
            float2* p1 = (float2*)(C + (size_t)(mbase + 8) * N + nb);
            *p0 = make_float2(c[mt][nt][0] + b0, c[mt][nt][1] + b1);
            *p1 = make_float2(c[mt][nt][2] + b0, c[mt][nt][3] + b1);
        }
    }
}

// ===========================================================================
// Tensor-core flash attention (bf16x3 split precision, FA2-style)
// CTA: 128 q-rows of one (b,h). 8 warps x 16 rows. KV chunks of 64.
// ===========================================================================
#define AQ   128
#define AKV  64
#define ALD  72
#define SMQ_HI 0
#define SMQ_LO (SMQ_HI + AQ * ALD * 2)
#define SMK_HI (SMQ_LO + AQ * ALD * 2)
#define SMK_LO (SMK_HI + AKV * ALD * 2)
#define SMV_HI (SMK_LO + AKV * ALD * 2)
#define SMV_LO (SMV_HI + AKV * ALD * 2)
#define SM_ATT_TOTAL (SMV_LO + AKV * ALD * 2)   // 73728 B

__global__ __launch_bounds__(256, 2) void attn_tc(const float* __restrict__ mask)
{
    extern __shared__ char sm[];
    const uint32_t smb = smem_u32(sm);
    const int tid = threadIdx.x;
    const int wid = tid >> 5;
    const int lane = tid & 31;
    const int b = blockIdx.y >> 4;
    const int h = blockIdx.y & 15;
    const int q0 = blockIdx.x << 7;
    const int wq = wid << 4;          // warp's 16-row band
    const int r0 = lane >> 2;
    const int cc = (lane & 3) << 1;

    const float* Qg = g_q + ((size_t)(b * Sq + q0)) * Dm + h * 64;
    const float* Kg = g_k + ((size_t)(b * Sq)) * Dm + h * 64;
    const float* Vg = g_v + ((size_t)(b * Sq)) * Dm + h * 64;

    // ---- stage Q: 128 rows x 16 float4 = 2048 units (8 per thread)  [R4 bugfix]
#pragma unroll
    for (int l = 0; l < 8; l++) {
        int idx = tid + (l << 8);
        int r  = idx >> 4;
        int d4 = (idx & 15) << 2;
        float4 q = *(const float4*)(Qg + (size_t)r * Dm + d4);
        uint32_t h01, h23, l01, l23;
        split2(q.x * 0.125f, q.y * 0.125f, h01, l01);
        split2(q.z * 0.125f, q.w * 0.125f, h23, l23);
        uint32_t off = (uint32_t)(r * ALD + d4) * 2u;
        *(uint2*)(sm + SMQ_HI + off) = make_uint2(h01, h23);
        *(uint2*)(sm + SMQ_LO + off) = make_uint2(l01, l23);
    }

    float o[8][4];
#pragma unroll
    for (int nt = 0; nt < 8; nt++)
#pragma unroll
        for (int r = 0; r < 4; r++) o[nt][r] = 0.f;
    float m0 = -1e30f, m1 = -1e30f, l0 = 0.f, l1 = 0.f;

    const uint32_t a_lrow = (uint32_t)(lane & 15);
    const uint32_t a_lcol = (uint32_t)(lane >> 4) * 16u;
    const uint32_t b_lrow = (uint32_t)(lane & 7);
    const uint32_t b_lcol = (uint32_t)((lane >> 3) & 1) * 16u;

    for (int kt = 0; kt < Sq / AKV; kt++) {
        const int k0 = kt << 6;
        __syncthreads();   // previous iteration's frag reads done

        // ---- stage K [kv][d] (direct) + V [d][kv] (transposed), split hi/lo
#pragma unroll
        for (int l = 0; l < 4; l++) {
            int idx = tid + (l << 8);
            int kv = idx >> 4;
            int d4 = (idx & 15) << 2;
            float4 kk = *(const float4*)(Kg + (size_t)(k0 + kv) * Dm + d4);
            uint32_t h01, h23, l01, l23;
            split2(kk.x, kk.y, h01, l01);
            split2(kk.z, kk.w, h23, l23);
            uint32_t off = (uint32_t)(kv * ALD + d4) * 2u;
            *(uint2*)(sm + SMK_HI + off) = make_uint2(h01, h23);
            *(uint2*)(sm + SMK_LO + off) = make_uint2(l01, l23);

            float4 vv = *(const float4*)(Vg + (size_t)(k0 + kv) * Dm + d4);
            float va[4] = {vv.x, vv.y, vv.z, vv.w};
#pragma unroll
            for (int j = 0; j < 4; j++) {
                __nv_bfloat16 vh = __float2bfloat16(va[j]);
                __nv_bfloat16 vl = __float2bfloat16(va[j] - __bfloat162float(vh));
                uint32_t voff = (uint32_t)((d4 + j) * ALD + kv) * 2u;
                *(__nv_bfloat16*)(sm + SMV_HI + voff) = vh;
                *(__nv_bfloat16*)(sm + SMV_LO + voff) = vl;
            }
        }
        __syncthreads();

        // ---- S = Q @ K^T  (scores, scaled)
        float s[8][4];
#pragma unroll
        for (int nt = 0; nt < 8; nt++)
#pragma unroll
            for (int r = 0; r < 4; r++) s[nt][r] = 0.f;

#pragma unroll
        for (int ks = 0; ks < 4; ks++) {
            uint32_t qoff = ((uint32_t)wq + a_lrow) * (ALD * 2u) + a_lcol + (uint32_t)(ks << 5);
            uint32_t ah[4], al[4];
            ldm_x4(ah, smb + SMQ_HI + qoff);
            ldm_x4(al, smb + SMQ_LO + qoff);
#pragma unroll
            for (int nt = 0; nt < 8; nt++) {
                uint32_t koff = ((uint32_t)(nt << 3) + b_lrow) * (ALD * 2u) + b_lcol + (uint32_t)(ks << 5);
                uint32_t kh[2], kl[2];
                ldm_x2(kh, smb + SMK_HI + koff);
                ldm_x2(kl, smb + SMK_LO + koff);
                mma_bf16(s[nt], ah, kh);
                mma_bf16(s[nt], ah, kl);
                mma_bf16(s[nt], al, kh);
            }
        }

        // ---- additive mask
        const float* mrow = mask + (size_t)(q0 + wq + r0) * Sq + k0 + cc;
#pragma unroll
        for (int nt = 0; nt < 8; nt++) {
            float2 ma = *(const float2*)(mrow + (nt << 3));
            float2 mb = *(const float2*)(mrow + 8 * Sq + (nt << 3));
            s[nt][0] = fmaf(ma.x, -1e9f, s[nt][0]);
            s[nt][1] = fmaf(ma.y, -1e9f, s[nt][1]);
            s[nt][2] = fmaf(mb.x, -1e9f, s[nt][2]);
            s[nt][3] = fmaf(mb.y, -1e9f, s[nt][3]);
        }

        // ---- online softmax (rows r0 and r0+8 per thread)
        float mx0 = s[0][0], mx1 = s[0][2];
#pragma unroll
        for (int nt = 0; nt < 8; nt++) {
            mx0 = fmaxf(mx0, fmaxf(s[nt][0], s[nt][1]));
            mx1 = fmaxf(mx1, fmaxf(s[nt][2], s[nt][3]));
        }
        mx0 = fmaxf(mx0, __shfl_xor_sync(0xffffffffu, mx0, 1));
        mx0 = fmaxf(mx0, __shfl_xor_sync(0xffffffffu, mx0, 2));
        mx1 = fmaxf(mx1, __shfl_xor_sync(0xffffffffu, mx1, 1));
        mx1 = fmaxf(mx1, __shfl_xor_sync(0xffffffffu, mx1, 2));

        float mn0 = fmaxf(m0, mx0);
        float mn1 = fmaxf(m1, mx1);
        float c0 = __expf(m0 - mn0);
        float c1 = __expf(m1 - mn1);
        m0 = mn0;
        m1 = mn1;

        float s0 = 0.f, s1 = 0.f;
#pragma unroll
        for (int nt = 0; nt < 8; nt++) {
            s[nt][0] = __expf(s[nt][0] - mn0);
            s[nt][1] = __expf(s[nt][1] - mn0);
            s[nt][2] = __expf(s[nt][2] - mn1);
            s[nt][3] = __expf(s[nt][3] - mn1);
            s0 += s[nt][0] + s[nt][1];
            s1 += s[nt][2] + s[nt][3];
        }
        s0 += __shfl_xor_sync(0xffffffffu, s0, 1);
        s0 += __shfl_xor_sync(0xffffffffu, s0, 2);
        s1 += __shfl_xor_sync(0xffffffffu, s1, 1);
        s1 += __shfl_xor_sync(0xffffffffu, s1, 2);
        l0 = l0 * c0 + s0;
        l1 = l1 * c1 + s1;

#pragma unroll
        for (int nt = 0; nt < 8; nt++) {
            o[nt][0] *= c0;
            o[nt][1] *= c0;
            o[nt][2] *= c1;
            o[nt][3] *= c1;
        }

        // ---- O += P @ V  (P from regs via C->A layout identity)
#pragma unroll
        for (int ks = 0; ks < 4; ks++) {
            uint32_t ph[4], pl[4];
            split2(s[2 * ks][0],     s[2 * ks][1],     ph[0], pl[0]);
            split2(s[2 * ks][2],     s[2 * ks][3],     ph[1], pl[1]);
            split2(s[2 * ks + 1][0], s[2 * ks + 1][1], ph[2], pl[2]);
            split2(s[2 * ks + 1][2], s[2 * ks + 1][3], ph[3], pl[3]);
#pragma unroll
            for (int nt = 0; nt < 8; nt++) {
                uint32_t voff = ((uint32_t)(nt << 3) + b_lrow) * (ALD * 2u) + b_lcol + (uint32_t)(ks << 5);
                uint32_t vh[2], vl[2];
                ldm_x2(vh, smb + SMV_HI + voff);
                ldm_x2(vl, smb + SMV_LO + voff);
                mma_bf16(o[nt], ph, vh);
                mma_bf16(o[nt], ph, vl);
                mma_bf16(o[nt], pl, vh);
            }
        }
    }

    // ---- epilogue: normalize, write ctx
    float inv0 = 1.f / l0;
    float inv1 = 1.f / l1;
    float* Og = g_ctx + (size_t)(b * Sq + q0 + wq) * Dm + h * 64;
#pragma unroll
    for (int nt = 0; nt < 8; nt++) {
        *(float2*)(Og + (size_t)r0 * Dm + (nt << 3) + cc) =
            make_float2(o[nt][0] * inv0, o[nt][1] * inv0);
        *(float2*)(Og + (size_t)(r0 + 8) * Dm + (nt << 3) + cc) =
            make_float2(o[nt][2] * inv1, o[nt][3] * inv1);
    }
}

// ---------------------------------------------------------------------------
// kernel_launch
// ---------------------------------------------------------------------------
extern "C" void kernel_launch(void* const* d_in, const int* in_sizes, int n_in,
                              void* d_out, int out_size)
{
    const float* queries = (const float*)d_in[0];
    const float* keys    = (const float*)d_in[1];
    const float* values  = (const float*)d_in[2];
    const float* mask    = (const float*)d_in[3];
    const float* Wq = (const float*)d_in[4];
    const float* bq = (const float*)d_in[5];
    const float* Wk = (const float*)d_in[6];
    const float* bk = (const float*)d_in[7];
    const float* Wv = (const float*)d_in[8];
    const float* bv = (const float*)d_in[9];
    const float* Wo = (const float*)d_in[10];
    const float* bo = (const float*)d_in[11];
    float* out = (float*)d_out;

    float *pq, *pk, *pv, *pctx;
    cudaGetSymbolAddress((void**)&pq,   g_q);
    cudaGetSymbolAddress((void**)&pk,   g_k);
    cudaGetSymbolAddress((void**)&pv,   g_v);
    cudaGetSymbolAddress((void**)&pctx, g_ctx);

    const int M = Bq * Sq;   // 8192
    const int N = Dm;        // 1024
    const int K = Dm;        // 1024

    cudaFuncSetAttribute(gemm_tc, cudaFuncAttributeMaxDynamicSharedMemorySize,
                         SM_GEMM_TOTAL);
    cudaFuncSetAttribute(attn_tc, cudaFuncAttributeMaxDynamicSharedMemorySize,
                         SM_ATT_TOTAL);

    dim3 gblk(256);
    dim3 ggrid(N / 128, M / 128);   // (8, 64)

    // QKV projections (HMMA bf16x3)
    gemm_tc<<<ggrid, gblk, SM_GEMM_TOTAL>>>(queries, Wq, bq, pq, M, N, K);
    gemm_tc<<<ggrid, gblk, SM_GEMM_TOTAL>>>(keys,    Wk, bk, pk, M, N, K);
    gemm_tc<<<ggrid, gblk, SM_GEMM_TOTAL>>>(values,  Wv, bv, pv, M, N, K);

    // Tensor-core flash attention
    dim3 agrid(Sq / AQ, Bq * Hh);   // (16, 64)
    attn_tc<<<agrid, gblk, SM_ATT_TOTAL>>>(mask);

    // Output projection (HMMA bf16x3)
    gemm_tc<<<ggrid, gblk, SM_GEMM_TOTAL>>>(pctx, Wo, bo, out, M, N, K);
}

// round 6
// speedup vs baseline: 2.8982x; 1.1398x over previous
#include <cuda_runtime.h>
#include <cuda_bf16.h>
#include <cstdint>
#include <math.h>

// Problem constants
#define Bq   4
#define Sq   2048
#define Dm   1024
#define Hh   16
#define DKh  64

// Scratch (device globals: allowed). q/k/v as pre-split bf16 hi/lo, [B,S,H*64].
__device__ __nv_bfloat16 g_qh[Bq * Sq * Dm];
__device__ __nv_bfloat16 g_ql[Bq * Sq * Dm];
__device__ __nv_bfloat16 g_kh[Bq * Sq * Dm];
__device__ __nv_bfloat16 g_kl[Bq * Sq * Dm];
__device__ __nv_bfloat16 g_vh[Bq * Sq * Dm];
__device__ __nv_bfloat16 g_vl[Bq * Sq * Dm];
__device__ float g_ctx[Bq * Sq * Dm];

// ===========================================================================
// helpers (baseline PTX, legal in compute_103)
// ===========================================================================
__device__ __forceinline__ uint32_t smem_u32(const void* p) {
    uint32_t a;
    asm("{ .reg .u64 t; cvta.to.shared.u64 t, %1; cvt.u32.u64 %0, t; }"
        : "=r"(a) : "l"(p));
    return a;
}
__device__ __forceinline__ void ldm_x4(uint32_t* r, uint32_t addr) {
    asm volatile("ldmatrix.sync.aligned.m8n8.x4.shared.b16 {%0,%1,%2,%3}, [%4];"
                 : "=r"(r[0]), "=r"(r[1]), "=r"(r[2]), "=r"(r[3]) : "r"(addr));
}
__device__ __forceinline__ void ldm_x4t(uint32_t* r, uint32_t addr) {
    asm volatile("ldmatrix.sync.aligned.m8n8.x4.trans.shared.b16 {%0,%1,%2,%3}, [%4];"
                 : "=r"(r[0]), "=r"(r[1]), "=r"(r[2]), "=r"(r[3]) : "r"(addr));
}
__device__ __forceinline__ void ldm_x2(uint32_t* r, uint32_t addr) {
    asm volatile("ldmatrix.sync.aligned.m8n8.x2.shared.b16 {%0,%1}, [%2];"
                 : "=r"(r[0]), "=r"(r[1]) : "r"(addr));
}
__device__ __forceinline__ void mma_bf16(float* c, const uint32_t* a, const uint32_t* b) {
    asm volatile(
        "mma.sync.aligned.m16n8k16.row.col.f32.bf16.bf16.f32 "
        "{%0,%1,%2,%3}, {%4,%5,%6,%7}, {%8,%9}, {%0,%1,%2,%3};"
        : "+f"(c[0]), "+f"(c[1]), "+f"(c[2]), "+f"(c[3])
        : "r"(a[0]), "r"(a[1]), "r"(a[2]), "r"(a[3]), "r"(b[0]), "r"(b[1]));
}
__device__ __forceinline__ void split2(float a, float b, uint32_t& hi, uint32_t& lo) {
    __nv_bfloat162 h = __float22bfloat162_rn(make_float2(a, b));
    float ra = a - __bfloat162float(h.x);
    float rb = b - __bfloat162float(h.y);
    __nv_bfloat162 l = __float22bfloat162_rn(make_float2(ra, rb));
    hi = *(uint32_t*)&h;
    lo = *(uint32_t*)&l;
}
__device__ __forceinline__ void cpa16(uint32_t dst, const void* src) {
    asm volatile("cp.async.cg.shared.global [%0], [%1], 16;" :: "r"(dst), "l"(src));
}
__device__ __forceinline__ void cp_commit() {
    asm volatile("cp.async.commit_group;" ::: "memory");
}
template <int N>
__device__ __forceinline__ void cp_wait() {
    asm volatile("cp.async.wait_group %0;" :: "n"(N) : "memory");
}

// ===========================================================================
// bf16x3 split-precision GEMM core (shared between the two epilogues)
// CTA: 128x128 C tile, BK=64, 8 warps (2m x 4n), warp 64x32.
// ===========================================================================
#define BK      64
#define LDT     72
#define A_TILE  (128 * LDT * 2)
#define B_TILE  (128 * LDT * 2)
#define SM_A_HI 0
#define SM_A_LO (SM_A_HI + A_TILE)
#define SM_B_HI (SM_A_LO + A_TILE)
#define SM_B_LO (SM_B_HI + B_TILE)
#define SM_GEMM_TOTAL (SM_B_LO + B_TILE)   // 73728 B

__device__ __forceinline__ void gemm_core(
    const float* __restrict__ A, const float* __restrict__ W,
    char* sm, uint32_t smb, int N, int K, int m0, int n0,
    float c[4][4][4])
{
    const int tid = threadIdx.x;
    const int lane = tid & 31;
    const int wid = tid >> 5;
    const int wm = wid >> 2;
    const int wn = wid & 3;

    const uint32_t a_lrow = (uint32_t)(lane & 15);
    const uint32_t a_lcol = (uint32_t)(lane >> 4) * 16u;
    const uint32_t b_lrow = (uint32_t)(lane & 7);
    const uint32_t b_lcol = (uint32_t)((lane >> 3) & 1) * 16u;

    for (int k0 = 0; k0 < K; k0 += BK) {
#pragma unroll
        for (int l = 0; l < 8; l++) {
            int idx = tid + (l << 8);
            int r  = idx >> 4;
            int c4 = (idx & 15) << 2;
            float4 a = *(const float4*)(A + (size_t)(m0 + r) * K + k0 + c4);
            uint32_t h01, h23, l01, l23;
            split2(a.x, a.y, h01, l01);
            split2(a.z, a.w, h23, l23);
            uint32_t off = (uint32_t)(r * LDT + c4) * 2u;
            *(uint2*)(sm + SM_A_HI + off) = make_uint2(h01, h23);
            *(uint2*)(sm + SM_A_LO + off) = make_uint2(l01, l23);
        }
#pragma unroll
        for (int l = 0; l < 8; l++) {
            int n  = (tid & 31) + ((l & 3) << 5);
            int kb = (((tid >> 5) + ((l >> 2) << 3)) << 2);
            const float* wp = W + (size_t)(k0 + kb) * N + n0 + n;
            float v0 = wp[0];
            float v1 = wp[N];
            float v2 = wp[2 * N];
            float v3 = wp[3 * N];
            uint32_t h01, h23, l01, l23;
            split2(v0, v1, h01, l01);
            split2(v2, v3, h23, l23);
            uint32_t off = (uint32_t)(n * LDT + kb) * 2u;
            *(uint2*)(sm + SM_B_HI + off) = make_uint2(h01, h23);
            *(uint2*)(sm + SM_B_LO + off) = make_uint2(l01, l23);
        }
        __syncthreads();

#pragma unroll
        for (int ks = 0; ks < 4; ks++) {
            const uint32_t kbyte = (uint32_t)ks * 32u;
            uint32_t ah[4][4], al[4][4], bh[4][2], bl[4][2];
#pragma unroll
            for (int mt = 0; mt < 4; mt++) {
                uint32_t row = (uint32_t)(wm * 64 + mt * 16) + a_lrow;
                uint32_t addr = row * (LDT * 2u) + a_lcol + kbyte;
                ldm_x4(ah[mt], smb + SM_A_HI + addr);
                ldm_x4(al[mt], smb + SM_A_LO + addr);
            }
#pragma unroll
            for (int nt = 0; nt < 4; nt++) {
                uint32_t row = (uint32_t)(wn * 32 + nt * 8) + b_lrow;
                uint32_t addr = row * (LDT * 2u) + b_lcol + kbyte;
                ldm_x2(bh[nt], smb + SM_B_HI + addr);
                ldm_x2(bl[nt], smb + SM_B_LO + addr);
            }
#pragma unroll
            for (int mt = 0; mt < 4; mt++)
#pragma unroll
                for (int nt = 0; nt < 4; nt++) {
                    mma_bf16(c[mt][nt], ah[mt], bh[nt]);
                    mma_bf16(c[mt][nt], ah[mt], bl[nt]);
                    mma_bf16(c[mt][nt], al[mt], bh[nt]);
                }
        }
        __syncthreads();
    }
}

// GEMM + bias -> fp32 C (output projection)
__global__ __launch_bounds__(256) void gemm_tc(
    const float* __restrict__ A, const float* __restrict__ W,
    const float* __restrict__ bias, float* __restrict__ C,
    int M, int N, int K)
{
    extern __shared__ char sm[];
    const uint32_t smb = smem_u32(sm);
    const int tid = threadIdx.x;
    const int lane = tid & 31;
    const int wid = tid >> 5;
    const int wm = wid >> 2;
    const int wn = wid & 3;
    const int m0 = blockIdx.y << 7;
    const int n0 = blockIdx.x << 7;

    float c[4][4][4];
#pragma unroll
    for (int i = 0; i < 4; i++)
#pragma unroll
        for (int j = 0; j < 4; j++)
#pragma unroll
            for (int r = 0; r < 4; r++) c[i][j][r] = 0.f;

    gemm_core(A, W, sm, smb, N, K, m0, n0, c);

    const int crow = lane >> 2;
    const int ccol = (lane & 3) << 1;
#pragma unroll
    for (int mt = 0; mt < 4; mt++) {
        const int mbase = m0 + wm * 64 + mt * 16 + crow;
#pragma unroll
        for (int nt = 0; nt < 4; nt++) {
            const int nb = n0 + wn * 32 + nt * 8 + ccol;
            float b0 = bias[nb], b1 = bias[nb + 1];
            *(float2*)(C + (size_t)mbase * N + nb) =
                make_float2(c[mt][nt][0] + b0, c[mt][nt][1] + b1);
            *(float2*)(C + (size_t)(mbase + 8) * N + nb) =
                make_float2(c[mt][nt][2] + b0, c[mt][nt][3] + b1);
        }
    }
}

// GEMM + bias -> scaled, pre-split bf16 hi/lo (q/k/v projections)
__global__ __launch_bounds__(256) void gemm_qkv(
    const float* __restrict__ A, const float* __restrict__ W,
    const float* __restrict__ bias,
    __nv_bfloat16* __restrict__ outH, __nv_bfloat16* __restrict__ outL,
    int M, int N, int K, float scale)
{
    extern __shared__ char sm[];
    const uint32_t smb = smem_u32(sm);
    const int tid = threadIdx.x;
    const int lane = tid & 31;
    const int wid = tid >> 5;
    const int wm = wid >> 2;
    const int wn = wid & 3;
    const int m0 = blockIdx.y << 7;
    const int n0 = blockIdx.x << 7;

    float c[4][4][4];
#pragma unroll
    for (int i = 0; i < 4; i++)
#pragma unroll
        for (int j = 0; j < 4; j++)
#pragma unroll
            for (int r = 0; r < 4; r++) c[i][j][r] = 0.f;

    gemm_core(A, W, sm, smb, N, K, m0, n0, c);

    const int crow = lane >> 2;
    const int ccol = (lane & 3) << 1;
#pragma unroll
    for (int mt = 0; mt < 4; mt++) {
        const int mbase = m0 + wm * 64 + mt * 16 + crow;
#pragma unroll
        for (int nt = 0; nt < 4; nt++) {
            const int nb = n0 + wn * 32 + nt * 8 + ccol;
            float b0 = bias[nb], b1 = bias[nb + 1];
            float v0 = (c[mt][nt][0] + b0) * scale;
            float v1 = (c[mt][nt][1] + b1) * scale;
            float v2 = (c[mt][nt][2] + b0) * scale;
            float v3 = (c[mt][nt][3] + b1) * scale;
            uint32_t hi, lo;
            split2(v0, v1, hi, lo);
            *(uint32_t*)(outH + (size_t)mbase * N + nb) = hi;
            *(uint32_t*)(outL + (size_t)mbase * N + nb) = lo;
            split2(v2, v3, hi, lo);
            *(uint32_t*)(outH + (size_t)(mbase + 8) * N + nb) = hi;
            *(uint32_t*)(outL + (size_t)(mbase + 8) * N + nb) = lo;
        }
    }
}

// ===========================================================================
// Tensor-core flash attention, cp.async double-buffered, pre-split bf16 I/O.
// CTA: 128 q-rows of one (b,h). 8 warps x 16 rows. KV chunks of 64.
// smem rows: 64 bf16 = 128B, XOR-16B swizzle (conflict-free ldmatrix, no pad).
// ===========================================================================
#define SMQ_H  0
#define SMQ_L  16384
#define STG0   32768            // per stage: KH 8192 | KL 8192 | VH 8192 | VL 8192
#define STG_SZ 32768
#define OFF_KH 0
#define OFF_KL 8192
#define OFF_VH 16384
#define OFF_VL 24576
#define SM_ATT_TOTAL (STG0 + 2 * STG_SZ)   // 98304 B

__device__ __forceinline__ uint32_t swz(uint32_t row, uint32_t c16) {
    return row * 128u + ((c16 ^ (row & 7u)) << 4);
}

__global__ __launch_bounds__(256, 2) void attn_tc(const float* __restrict__ mask)
{
    extern __shared__ char sm[];
    const uint32_t smb = smem_u32(sm);
    const int tid = threadIdx.x;
    const int wid = tid >> 5;
    const int lane = tid & 31;
    const int b = blockIdx.y >> 4;
    const int h = blockIdx.y & 15;
    const int q0 = blockIdx.x << 7;
    const int wq = wid << 4;
    const int r0 = lane >> 2;
    const int cc = (lane & 3) << 1;

    const size_t rowbase = (size_t)(b * Sq) * Dm + h * 64;   // element offset of s=0

    // ---- issue Q staging (hi+lo): 128 rows x 8 chunks x 2 = 2048, 8/thread
    {
        const char* qh = (const char*)(g_qh + rowbase + (size_t)q0 * Dm);
        const char* ql = (const char*)(g_ql + rowbase + (size_t)q0 * Dm);
#pragma unroll
        for (int l = 0; l < 4; l++) {
            int idx = tid + (l << 8);        // 0..1023 : rows x chunks
            uint32_t r = (uint32_t)(idx >> 3);
            uint32_t c = (uint32_t)(idx & 7);
            uint32_t d = swz(r, c);
            cpa16(smb + SMQ_H + d, qh + (size_t)r * 2048 + c * 16);
            cpa16(smb + SMQ_L + d, ql + (size_t)r * 2048 + c * 16);
        }
    }
    // ---- issue KV chunk 0 into stage 0
    const char* kh_g = (const char*)(g_kh + rowbase);
    const char* kl_g = (const char*)(g_kl + rowbase);
    const char* vh_g = (const char*)(g_vh + rowbase);
    const char* vl_g = (const char*)(g_vl + rowbase);
    {
        uint32_t sb = smb + STG0;
#pragma unroll
        for (int l = 0; l < 2; l++) {
            int idx = tid + (l << 8);        // 0..511
            uint32_t r = (uint32_t)(idx >> 3);
            uint32_t c = (uint32_t)(idx & 7);
            uint32_t d = swz(r, c);
            size_t src = (size_t)r * 2048 + c * 16;
            cpa16(sb + OFF_KH + d, kh_g + src);
            cpa16(sb + OFF_KL + d, kl_g + src);
            cpa16(sb + OFF_VH + d, vh_g + src);
            cpa16(sb + OFF_VL + d, vl_g + src);
        }
    }
    cp_commit();

    float o[8][4];
#pragma unroll
    for (int nt = 0; nt < 8; nt++)
#pragma unroll
        for (int r = 0; r < 4; r++) o[nt][r] = 0.f;
    float m0 = -1e30f, m1 = -1e30f, l0 = 0.f, l1 = 0.f;

    // per-lane fragment address components
    const uint32_t q_row = (uint32_t)wq + (uint32_t)(lane & 15);
    const uint32_t q_c   = (uint32_t)(lane >> 4);
    const uint32_t k_row = (uint32_t)(lane & 7) + ((uint32_t)(lane >> 4) & 1u) * 8u;
    const uint32_t k_c   = (uint32_t)((lane >> 3) & 1);
    const uint32_t v_row = (uint32_t)(lane & 7) + (((uint32_t)lane >> 3) & 1u) * 8u;
    const uint32_t v_c   = (uint32_t)(lane >> 4);

    for (int kt = 0; kt < Sq / 64; kt++) {
        // ---- prefetch next chunk into the other stage
        if (kt + 1 < Sq / 64) {
            uint32_t sb = smb + STG0 + ((kt + 1) & 1) * STG_SZ;
            size_t gsrc0 = (size_t)(kt + 1) * 64 * 2048;
#pragma unroll
            for (int l = 0; l < 2; l++) {
                int idx = tid + (l << 8);
                uint32_t r = (uint32_t)(idx >> 3);
                uint32_t c = (uint32_t)(idx & 7);
                uint32_t d = swz(r, c);
                size_t src = gsrc0 + (size_t)r * 2048 + c * 16;
                cpa16(sb + OFF_KH + d, kh_g + src);
                cpa16(sb + OFF_KL + d, kl_g + src);
                cpa16(sb + OFF_VH + d, vh_g + src);
                cpa16(sb + OFF_VL + d, vl_g + src);
            }
            cp_commit();
            cp_wait<1>();
        } else {
            cp_wait<0>();
        }
        __syncthreads();

        const uint32_t sb = smb + STG0 + (kt & 1) * STG_SZ;
        const int k0 = kt << 6;

        // ---- S = Q @ K^T
        float s[8][4];
#pragma unroll
        for (int nt = 0; nt < 8; nt++)
#pragma unroll
            for (int r = 0; r < 4; r++) s[nt][r] = 0.f;

#pragma unroll
        for (int ks = 0; ks < 4; ks++) {
            uint32_t qaddr = swz(q_row, (uint32_t)(ks << 1) + q_c);
            uint32_t ah[4], al[4];
            ldm_x4(ah, smb + SMQ_H + qaddr);
            ldm_x4(al, smb + SMQ_L + qaddr);
#pragma unroll
            for (int p = 0; p < 4; p++) {
                uint32_t kaddr = swz((uint32_t)(p << 4) + k_row, (uint32_t)(ks << 1) + k_c);
                uint32_t kh[4], kl[4];
                ldm_x4(kh, sb + OFF_KH + kaddr);
                ldm_x4(kl, sb + OFF_KL + kaddr);
                mma_bf16(s[2 * p],     ah, kh);
                mma_bf16(s[2 * p],     ah, kl);
                mma_bf16(s[2 * p],     al, kh);
                mma_bf16(s[2 * p + 1], ah, kh + 2);
                mma_bf16(s[2 * p + 1], ah, kl + 2);
                mma_bf16(s[2 * p + 1], al, kh + 2);
            }
        }

        // ---- additive mask
        const float* mrow = mask + (size_t)(q0 + wq + r0) * Sq + k0 + cc;
#pragma unroll
        for (int nt = 0; nt < 8; nt++) {
            float2 ma = *(const float2*)(mrow + (nt << 3));
            float2 mb = *(const float2*)(mrow + 8 * Sq + (nt << 3));
            s[nt][0] = fmaf(ma.x, -1e9f, s[nt][0]);
            s[nt][1] = fmaf(ma.y, -1e9f, s[nt][1]);
            s[nt][2] = fmaf(mb.x, -1e9f, s[nt][2]);
            s[nt][3] = fmaf(mb.y, -1e9f, s[nt][3]);
        }

        // ---- online softmax (rows r0, r0+8)
        float mx0 = s[0][0], mx1 = s[0][2];
#pragma unroll
        for (int nt = 0; nt < 8; nt++) {
            mx0 = fmaxf(mx0, fmaxf(s[nt][0], s[nt][1]));
            mx1 = fmaxf(mx1, fmaxf(s[nt][2], s[nt][3]));
        }
        mx0 = fmaxf(mx0, __shfl_xor_sync(0xffffffffu, mx0, 1));
        mx0 = fmaxf(mx0, __shfl_xor_sync(0xffffffffu, mx0, 2));
        mx1 = fmaxf(mx1, __shfl_xor_sync(0xffffffffu, mx1, 1));
        mx1 = fmaxf(mx1, __shfl_xor_sync(0xffffffffu, mx1, 2));

        float mn0 = fmaxf(m0, mx0);
        float mn1 = fmaxf(m1, mx1);
        float c0 = __expf(m0 - mn0);
        float c1 = __expf(m1 - mn1);
        m0 = mn0;
        m1 = mn1;

        float s0 = 0.f, s1 = 0.f;
#pragma unroll
        for (int nt = 0; nt < 8; nt++) {
            s[nt][0] = __expf(s[nt][0] - mn0);
            s[nt][1] = __expf(s[nt][1] - mn0);
            s[nt][2] = __expf(s[nt][2] - mn1);
            s[nt][3] = __expf(s[nt][3] - mn1);
            s0 += s[nt][0] + s[nt][1];
            s1 += s[nt][2] + s[nt][3];
        }
        s0 += __shfl_xor_sync(0xffffffffu, s0, 1);
        s0 += __shfl_xor_sync(0xffffffffu, s0, 2);
        s1 += __shfl_xor_sync(0xffffffffu, s1, 1);
        s1 += __shfl_xor_sync(0xffffffffu, s1, 2);
        l0 = l0 * c0 + s0;
        l1 = l1 * c1 + s1;

#pragma unroll
        for (int nt = 0; nt < 8; nt++) {
            o[nt][0] *= c0;
            o[nt][1] *= c0;
            o[nt][2] *= c1;
            o[nt][3] *= c1;
        }

        // ---- O += P @ V  (P from regs, V fragments via ldmatrix.trans)
#pragma unroll
        for (int ks = 0; ks < 4; ks++) {
            uint32_t ph[4], pl[4];
            split2(s[2 * ks][0],     s[2 * ks][1],     ph[0], pl[0]);
            split2(s[2 * ks][2],     s[2 * ks][3],     ph[1], pl[1]);
            split2(s[2 * ks + 1][0], s[2 * ks + 1][1], ph[2], pl[2]);
            split2(s[2 * ks + 1][2], s[2 * ks + 1][3], ph[3], pl[3]);
            uint32_t vrow = (uint32_t)(ks << 4) + v_row;
#pragma unroll
            for (int p = 0; p < 4; p++) {
                uint32_t vaddr = swz(vrow, (uint32_t)(p << 1) + v_c);
                uint32_t vh[4], vl[4];
                ldm_x4t(vh, sb + OFF_VH + vaddr);
                ldm_x4t(vl, sb + OFF_VL + vaddr);
                mma_bf16(o[2 * p],     ph, vh);
                mma_bf16(o[2 * p],     ph, vl);
                mma_bf16(o[2 * p],     pl, vh);
                mma_bf16(o[2 * p + 1], ph, vh + 2);
                mma_bf16(o[2 * p + 1], ph, vl + 2);
                mma_bf16(o[2 * p + 1], pl, vh + 2);
            }
        }
        __syncthreads();   // stage reuse protection for next prefetch
    }

    // ---- epilogue
    float inv0 = 1.f / l0;
    float inv1 = 1.f / l1;
    float* Og = g_ctx + (size_t)(b * Sq + q0 + wq) * Dm + h * 64;
#pragma unroll
    for (int nt = 0; nt < 8; nt++) {
        *(float2*)(Og + (size_t)r0 * Dm + (nt << 3) + cc) =
            make_float2(o[nt][0] * inv0, o[nt][1] * inv0);
        *(float2*)(Og + (size_t)(r0 + 8) * Dm + (nt << 3) + cc) =
            make_float2(o[nt][2] * inv1, o[nt][3] * inv1);
    }
}

// ---------------------------------------------------------------------------
// kernel_launch
// ---------------------------------------------------------------------------
extern "C" void kernel_launch(void* const* d_in, const int* in_sizes, int n_in,
                              void* d_out, int out_size)
{
    const float* queries = (const float*)d_in[0];
    const float* keys    = (const float*)d_in[1];
    const float* values  = (const float*)d_in[2];
    const float* mask    = (const float*)d_in[3];
    const float* Wq = (const float*)d_in[4];
    const float* bq = (const float*)d_in[5];
    const float* Wk = (const float*)d_in[6];
    const float* bk = (const float*)d_in[7];
    const float* Wv = (const float*)d_in[8];
    const float* bv = (const float*)d_in[9];
    const float* Wo = (const float*)d_in[10];
    const float* bo = (const float*)d_in[11];
    float* out = (float*)d_out;

    __nv_bfloat16 *pqh, *pql, *pkh, *pkl, *pvh, *pvl;
    float* pctx;
    cudaGetSymbolAddress((void**)&pqh, g_qh);
    cudaGetSymbolAddress((void**)&pql, g_ql);
    cudaGetSymbolAddress((void**)&pkh, g_kh);
    cudaGetSymbolAddress((void**)&pkl, g_kl);
    cudaGetSymbolAddress((void**)&pvh, g_vh);
    cudaGetSymbolAddress((void**)&pvl, g_vl);
    cudaGetSymbolAddress((void**)&pctx, g_ctx);

    const int M = Bq * Sq;   // 8192
    const int N = Dm;        // 1024
    const int K = Dm;        // 1024

    cudaFuncSetAttribute(gemm_tc,  cudaFuncAttributeMaxDynamicSharedMemorySize, SM_GEMM_TOTAL);
    cudaFuncSetAttribute(gemm_qkv, cudaFuncAttributeMaxDynamicSharedMemorySize, SM_GEMM_TOTAL);
    cudaFuncSetAttribute(attn_tc,  cudaFuncAttributeMaxDynamicSharedMemorySize, SM_ATT_TOTAL);

    dim3 gblk(256);
    dim3 ggrid(N / 128, M / 128);   // (8, 64)

    // QKV projections -> pre-split bf16 (Q pre-scaled by 1/8)
    gemm_qkv<<<ggrid, gblk, SM_GEMM_TOTAL>>>(queries, Wq, bq, pqh, pql, M, N, K, 0.125f);
    gemm_qkv<<<ggrid, gblk, SM_GEMM_TOTAL>>>(keys,    Wk, bk, pkh, pkl, M, N, K, 1.0f);
    gemm_qkv<<<ggrid, gblk, SM_GEMM_TOTAL>>>(values,  Wv, bv, pvh, pvl, M, N, K, 1.0f);

    // Flash attention (double-buffered cp.async)
    dim3 agrid(Sq / 128, Bq * Hh);   // (16, 64)
    attn_tc<<<agrid, gblk, SM_ATT_TOTAL>>>(mask);

    // Output projection
    gemm_tc<<<ggrid, gblk, SM_GEMM_TOTAL>>>(pctx, Wo, bo, out, M, N, K);
}